// round 15
// baseline (speedup 1.0000x reference)
#include <cuda_runtime.h>
#include <cuda_bf16.h>
#include <stdint.h>
#include <math.h>

#define NG 8
#define LG 1024
#define NH 8
#define HD 16
#define DS 64
#define NB 64
#define NE 131072
#define NN_NODES 8192
#define MSZ (64ULL * 1024 * 1024)

typedef __nv_bfloat16 bf16;

__device__ float g_S[MSZ];
__device__ float g_G[8ULL * 1024 * 1024];
// each logical matrix: hi plane at [0, MSZ), lo plane at [MSZ, 2*MSZ)
__device__ bf16 g_La[2 * MSZ], g_LaT[2 * MSZ];
__device__ bf16 g_Lb[2 * MSZ], g_LbT[2 * MSZ];
__device__ bf16 g_Oa[2 * MSZ], g_Ob[2 * MSZ];
__device__ float g_e0[NH * NN_NODES];
__device__ float g_e1[NH * NN_NODES];
__device__ float g_dummy[NH * NN_NODES];
__device__ float g_w[NH * NN_NODES];

// ---------------- helpers ----------------
__device__ __forceinline__ uint32_t smem_u32(const void* p) {
    uint32_t a;
    asm("{ .reg .u64 t; cvta.to.shared.u64 t, %1; cvt.u32.u64 %0, t; }" : "=r"(a) : "l"(p));
    return a;
}
#define CP16(dst, src) asm volatile("cp.async.cg.shared.global [%0], [%1], 16;" :: "r"(dst), "l"(src) : "memory")
#define CP_COMMIT()    asm volatile("cp.async.commit_group;" ::: "memory")
#define CP_WAIT1()     asm volatile("cp.async.wait_group 1;" ::: "memory")
#define CP_WAIT0()     asm volatile("cp.async.wait_group 0;" ::: "memory")
#define NBAR(id)       asm volatile("bar.sync %0, %1;" :: "r"(id), "r"(128) : "memory")

#define LDSM4(r, addr) \
    asm volatile("ldmatrix.sync.aligned.m8n8.x4.shared.b16 {%0,%1,%2,%3}, [%4];" \
        : "=r"((r)[0]), "=r"((r)[1]), "=r"((r)[2]), "=r"((r)[3]) : "r"(addr))

#define MMA16816(d, a, b0, b1) \
    asm volatile("mma.sync.aligned.m16n8k16.row.col.f32.bf16.bf16.f32 " \
        "{%0,%1,%2,%3}, {%4,%5,%6,%7}, {%8,%9}, {%0,%1,%2,%3};" \
        : "+f"((d)[0]), "+f"((d)[1]), "+f"((d)[2]), "+f"((d)[3]) \
        : "r"((a)[0]), "r"((a)[1]), "r"((a)[2]), "r"((a)[3]), "r"(b0), "r"(b1))

__device__ __forceinline__ float bf_lo(uint32_t u) { return __bfloat162float(__ushort_as_bfloat16((unsigned short)(u & 0xFFFF))); }
__device__ __forceinline__ float bf_hi(uint32_t u) { return __bfloat162float(__ushort_as_bfloat16((unsigned short)(u >> 16))); }
__device__ __forceinline__ void split_bf16(float v, bf16& h, bf16& l) {
    h = __float2bfloat16(v);
    l = __float2bfloat16(v - __bfloat162float(h));
}
__device__ __forceinline__ uint32_t pack2(bf16 a, bf16 b) {
    return ((uint32_t)__bfloat16_as_ushort(b) << 16) | __bfloat16_as_ushort(a);
}
__device__ __forceinline__ float softplusf(float x) { return (x > 15.f) ? x : log1pf(expf(x)); }

// swizzled offset inside a (rows x 64B) operand block: row r, 16B-chunk c (0..3)
__device__ __forceinline__ uint32_t swz(int r, int c) {
    return (uint32_t)(r * 64 + ((c ^ (r >> 1)) & 3) * 16);
}

// ---------------- fused zero + per-node prep ----------------
__global__ void k_zeronode(const float* __restrict__ dt, const float* __restrict__ dtb,
                           float* __restrict__ S) {
    int gid = blockIdx.x * blockDim.x + threadIdx.x;
    if (gid < NN_NODES * NH) {
        int n = gid >> 3, h = gid & 7;
        float b = dtb[h];
        const float* row = dt + (size_t)n * (NH * 4) + h * 4;
        g_e0[h * NN_NODES + n] = -softplusf(row[0] + b);
        g_e1[h * NN_NODES + n] = -softplusf(row[1] + b);
        g_dummy[h * NN_NODES + n] = expf(-softplusf(row[2] + b));
        g_w[h * NN_NODES + n] = row[3];
    }
    size_t i = (size_t)gid * 4;
    size_t st = (size_t)gridDim.x * blockDim.x * 4;
    float4 z = make_float4(0.f, 0.f, 0.f, 0.f);
    for (; i < MSZ; i += st) *(float4*)(S + i) = z;
}

// ---------------- edge scatter ----------------
__global__ void k_scatter(const int* __restrict__ ei) {
    int idx = blockIdx.x * blockDim.x + threadIdx.x;
    if (idx >= NE * NH) return;
    int e = idx >> 3, h = idx & 7;
    int s = ei[e], d = ei[NE + e];
    int b = s >> 10, sl = s & 1023, dl = d & 1023;
    float v = expf(0.5f * (g_e0[h * NN_NODES + s] + g_e1[h * NN_NODES + d]));
    atomicAdd(&g_S[(((size_t)(b * NH + h)) * LG + sl) * LG + dl], v);
}

// ---------------- fused norm + prep ----------------
__global__ void __launch_bounds__(256) k_normprep() {
    __shared__ float snrm[32];
    __shared__ float t[32][33];
    int bh = blockIdx.y;
    int j0 = blockIdx.x * 32;
    int b = bh >> 3, h = bh & 7;
    size_t off = (size_t)bh << 20;
    int tid = threadIdx.x;
    int wid = tid >> 5, lane = tid & 31;

    #pragma unroll
    for (int rr = 0; rr < 4; rr++) {
        int jj = wid * 4 + rr;
        const float* row = g_S + off + (size_t)(j0 + jj) * LG;
        float s = 0.f;
        for (int i = lane; i < LG; i += 32) s += row[i];
        #pragma unroll
        for (int o = 16; o; o >>= 1) s += __shfl_xor_sync(0xFFFFFFFFu, s, o);
        if (lane == 0)
            snrm[jj] = 1.f / (s + g_dummy[h * NN_NODES + b * LG + j0 + jj] + 0.1f);
    }
    __syncthreads();

    int tx = tid & 31, ty = tid >> 5;   // (32, 8)
    for (int i0 = 0; i0 < LG; i0 += 32) {
        #pragma unroll
        for (int k = 0; k < 4; k++) {
            int jj = ty + k * 8;
            float v = g_S[off + (size_t)(j0 + jj) * LG + i0 + tx];
            t[jj][tx] = v;
            float mt = v * snrm[jj];
            size_t o = off + (size_t)(j0 + jj) * LG + i0 + tx;
            bf16 hh, ll; split_bf16(mt, hh, ll);
            g_LaT[o] = hh; g_LaT[MSZ + o] = ll;
        }
        __syncthreads();
        #pragma unroll
        for (int k = 0; k < 4; k++) {
            int i = i0 + ty + k * 8;
            int j = j0 + tx;
            float v = t[tx][ty + k * 8] * snrm[tx];
            size_t o = off + (size_t)i * LG + j;
            bf16 hh, ll; split_bf16(v, hh, ll);
            g_La[o] = hh; g_La[MSZ + o] = ll;
            float w = v + ((i == j) ? 1.f : 0.f);
            split_bf16(w, hh, ll);
            g_Oa[o] = hh; g_Oa[MSZ + o] = ll;
        }
        __syncthreads();
    }
}

// ---------------- HMMA batched GEMM body: C = A@B (+Add), split bf16 x3 ----------------
// Tile 128x128. CTA split into two independent 4-warp halves (named barriers), each
// owning 64 N-columns with PRIVATE stage buffers (A duplicated per half).
// Per half per stage: A-hi 8K | A-lo 8K | B-hi 4K | B-lo 4K = 24KB. Stage = 48KB. 2 stages.
// Warp tile 64x32, KC=32, XOR-swizzled 64B rows, 1 named barrier/kt, B-hoist.
#define HALF_SZ  24576
#define STAGE_SZ 49152
#define MMA_SMEM (2 * STAGE_SZ)

__device__ __forceinline__ void mma_body(const bf16* __restrict__ A,
                                         const bf16* __restrict__ B,
                                         bf16* __restrict__ C,
                                         const bf16* __restrict__ Add,
                                         bf16* __restrict__ T,
                                         char* dsm, int zb,
                                         int bx, int by, int tid) {
    size_t moff = (size_t)zb << 20;
    A += moff; B += moff; C += moff;
    if (Add) Add += moff;
    if (T) T += moff;
    int row0 = by * 128, col0 = bx * 128;

    uint32_t sm0 = smem_u32(dsm);
    int wid = tid >> 5, lane = tid & 31;
    const int hf = wid >> 2;                       // half id: warps 0-3 -> 0, 4-7 -> 1
    int wm = (wid & 1) * 64;                       // M offset within tile
    int wnl = ((wid >> 1) & 1) * 32;               // N offset within half (0 or 32)
    int wng = hf * 64 + wnl;                       // global N offset within tile
    const uint32_t hb = (uint32_t)(hf * HALF_SZ);  // half base within stage

    float acc[4][4][4];
    #pragma unroll
    for (int i = 0; i < 4; i++)
        #pragma unroll
        for (int j = 0; j < 4; j++)
            #pragma unroll
            for (int k = 0; k < 4; k++) acc[i][j][k] = 0.f;

    const int ht = tid & 127;                      // thread index within half

    // per-half private loads: A full 128 rows (duplicated), B rows [hf*64, hf*64+64)
    auto preloadA = [&](int kt, uint32_t base) {   // base = stage + hb
        int r = ht;
        size_t go = (size_t)(row0 + r) * 1024 + kt * 32;
        #pragma unroll
        for (int c = 0; c < 4; c++) {
            uint32_t so = swz(r, c);
            CP16(base + so,        (const char*)(A + go + c * 8));
            CP16(base + 8192 + so, (const char*)(A + MSZ + go + c * 8));
        }
    };
    auto preloadB = [&](int kt, uint32_t base) {
        #pragma unroll
        for (int q = 0; q < 2; q++) {
            int r = (ht >> 2) + q * 32;            // local B row 0..63
            int c = ht & 3;
            uint32_t so = swz(r, c);
            size_t gb = (size_t)(col0 + hf * 64 + r) * 1024 + kt * 32 + c * 8;
            CP16(base + 16384 + so, (const char*)(B + gb));
            CP16(base + 20480 + so, (const char*)(B + MSZ + gb));
        }
        CP_COMMIT();
    };

    // persistent B fragments (hoisted across the step boundary for kh0)
    uint32_t bhf[2][4], blf[2][4];

    auto loadB = [&](uint32_t base, int kh) {      // base = stage + hb
        #pragma unroll
        for (int nj = 0; nj < 2; nj++) {
            int br = wnl + nj * 16 + (lane & 15);  // local B row
            uint32_t bd = base + 16384 + swz(br, kh * 2 + (lane >> 4));
            LDSM4(bhf[nj], bd);
            LDSM4(blf[nj], bd + 4096);
        }
    };

    auto computeA = [&](uint32_t base, int kh) {
        #pragma unroll
        for (int mi = 0; mi < 4; mi++) {
            uint32_t ah[4], al[4];
            int ar = wm + mi * 16 + (lane & 15);
            uint32_t ad = base + swz(ar, kh * 2 + (lane >> 4));
            LDSM4(ah, ad);
            LDSM4(al, ad + 8192);
            #pragma unroll
            for (int ni = 0; ni < 4; ni++) {
                int g = ni >> 1, w = ni & 1;
                MMA16816(acc[mi][ni], ah, bhf[g][w], bhf[g][2 + w]);   // Ah*Bh
            }
            #pragma unroll
            for (int ni = 0; ni < 4; ni++) {
                int g = ni >> 1, w = ni & 1;
                MMA16816(acc[mi][ni], ah, blf[g][w], blf[g][2 + w]);   // Ah*Bl
            }
            #pragma unroll
            for (int ni = 0; ni < 4; ni++) {
                int g = ni >> 1, w = ni & 1;
                MMA16816(acc[mi][ni], al, bhf[g][w], bhf[g][2 + w]);   // Al*Bh
            }
        }
    };

    const int barid = 1 + hf;
    // mode: 0 = prefetch kt+1 into pb + tail; 2 = last kt (no prefetch, no tail)
    auto step = [&](int kt, uint32_t ab, uint32_t pb, int mode) {
        // entry: kh0 B-frags in regs; stage ab ready for this half
        if (mode == 0) preloadA(kt + 1, pb);
        computeA(ab, 0);
        loadB(ab, 1);
        if (mode == 0) preloadB(kt + 1, pb);       // commit
        computeA(ab, 1);
        if (mode != 2) {
            CP_WAIT0();                            // own copies of group kt+1 done
            NBAR(barid);                           // half-wide visibility + stage reuse
            loadB(pb, 0);                          // next kt kh0 B-frags
        }
    };

    const uint32_t s0 = sm0 + hb, s1 = sm0 + STAGE_SZ + hb;
    preloadA(0, s0); preloadB(0, s0);
    preloadA(1, s1); preloadB(1, s1);
    CP_WAIT1();          // own G0 copies done
    NBAR(barid);         // half's G0 copies visible
    loadB(s0, 0);        // kt0 kh0 B-frags

    #pragma unroll 2
    for (int ktb = 0; ktb < 30; ktb += 2) {
        step(ktb,     s0, s1, 0);
        step(ktb + 1, s1, s0, 0);
    }
    step(30, s0, s1, 0);
    step(31, s1, s0, 2);

    // ---- epilogue ----
    __syncthreads();   // full CTA: smem reuse for transpose staging
    uint32_t* tb_h = (uint32_t*)dsm;          // [128][65] packed bf16x2
    uint32_t* tb_l = tb_h + 128 * 65;

    int rl = lane >> 2, cl = (lane & 3) * 2;
    #pragma unroll
    for (int mi = 0; mi < 4; mi++) {
        #pragma unroll
        for (int ni = 0; ni < 4; ni++) {
            int r1 = wm + mi * 16 + rl;
            int cc = wng + ni * 8 + cl;
            size_t rA = (size_t)(row0 + r1) * 1024 + col0 + cc;
            size_t rB = rA + 8 * 1024;
            float v0 = acc[mi][ni][0], v1 = acc[mi][ni][1];
            float v2 = acc[mi][ni][2], v3 = acc[mi][ni][3];
            if (Add) {
                uint32_t qh = *(const uint32_t*)(Add + rA), ql = *(const uint32_t*)(Add + MSZ + rA);
                v0 += bf_lo(qh) + bf_lo(ql);  v1 += bf_hi(qh) + bf_hi(ql);
                uint32_t rh = *(const uint32_t*)(Add + rB), rlq = *(const uint32_t*)(Add + MSZ + rB);
                v2 += bf_lo(rh) + bf_lo(rlq); v3 += bf_hi(rh) + bf_hi(rlq);
            }
            bf16 h0, l0, h1, l1;
            split_bf16(v0, h0, l0); split_bf16(v1, h1, l1);
            uint32_t ohA = pack2(h0, h1), olA = pack2(l0, l1);
            split_bf16(v2, h0, l0); split_bf16(v3, h1, l1);
            uint32_t ohB = pack2(h0, h1), olB = pack2(l0, l1);
            *(uint32_t*)(C + rA) = ohA;  *(uint32_t*)(C + MSZ + rA) = olA;
            *(uint32_t*)(C + rB) = ohB;  *(uint32_t*)(C + MSZ + rB) = olB;
            if (T) {
                tb_h[r1 * 65 + (cc >> 1)] = ohA;  tb_l[r1 * 65 + (cc >> 1)] = olA;
                tb_h[(r1 + 8) * 65 + (cc >> 1)] = ohB;  tb_l[(r1 + 8) * 65 + (cc >> 1)] = olB;
            }
        }
    }

    if (T) {
        __syncthreads();
        int c = tid >> 1, r0 = (tid & 1) * 64;
        const bf16* b16;
        size_t to = (size_t)(col0 + c) * 1024 + row0 + r0;
        b16 = (const bf16*)tb_h;
        {
            uint32_t o[32];
            #pragma unroll
            for (int r = 0; r < 64; r += 2)
                o[r >> 1] = pack2(b16[(r0 + r) * 130 + c], b16[(r0 + r + 1) * 130 + c]);
            #pragma unroll
            for (int w = 0; w < 8; w++)
                *(uint4*)(T + to + w * 8) = make_uint4(o[w*4], o[w*4+1], o[w*4+2], o[w*4+3]);
        }
        b16 = (const bf16*)tb_l;
        {
            uint32_t o[32];
            #pragma unroll
            for (int r = 0; r < 64; r += 2)
                o[r >> 1] = pack2(b16[(r0 + r) * 130 + c], b16[(r0 + r + 1) * 130 + c]);
            #pragma unroll
            for (int w = 0; w < 8; w++)
                *(uint4*)(T + MSZ + to + w * 8) = make_uint4(o[w*4], o[w*4+1], o[w*4+2], o[w*4+3]);
        }
    }
}

// dual-task GEMM kernel: z < nz0 -> set 0, else set 1 (batch index z - nz0)
__global__ void __launch_bounds__(256, 2) k_mma(const bf16* __restrict__ A0, const bf16* __restrict__ B0,
                                                bf16* __restrict__ C0, const bf16* __restrict__ Add0,
                                                bf16* __restrict__ T0,
                                                const bf16* __restrict__ A1, const bf16* __restrict__ B1,
                                                bf16* __restrict__ C1, const bf16* __restrict__ Add1,
                                                bf16* __restrict__ T1,
                                                int nz0) {
    extern __shared__ __align__(16) char dsm[];
    int z = blockIdx.z;
    const bf16 *A, *B, *Add; bf16 *C, *T; int zb;
    if (z < nz0) { A = A0; B = B0; C = C0; Add = Add0; T = T0; zb = z; }
    else         { A = A1; B = B1; C = C1; Add = Add1; T = T1; zb = z - nz0; }
    mma_body(A, B, C, Add, T, dsm, zb, blockIdx.x, blockIdx.y, threadIdx.x);
}

// ---------------- G[b,l,t] = sum_d C[b,l,d] * B[b,t,d] ----------------
__global__ void __launch_bounds__(256) k_gmat(const float* __restrict__ Cm,
                                              const float* __restrict__ Bm) {
    __shared__ float Cs[64][65];
    __shared__ float Bs2[64][65];
    int b = blockIdx.z;
    int t0 = blockIdx.x * 64, l0 = blockIdx.y * 64;
    int tid = threadIdx.x;
    #pragma unroll
    for (int q = 0; q < 4; q++) {
        int idx = tid + q * 256;
        int r = idx >> 4, c4 = (idx & 15) * 4;
        float4 v = *(const float4*)(Cm + ((size_t)(b * LG + l0 + r)) * DS + c4);
        Cs[r][c4] = v.x; Cs[r][c4 + 1] = v.y; Cs[r][c4 + 2] = v.z; Cs[r][c4 + 3] = v.w;
        float4 w = *(const float4*)(Bm + ((size_t)(b * LG + t0 + r)) * DS + c4);
        Bs2[r][c4] = w.x; Bs2[r][c4 + 1] = w.y; Bs2[r][c4 + 2] = w.z; Bs2[r][c4 + 3] = w.w;
    }
    __syncthreads();
    int tx = tid & 15, ty = tid >> 4;
    float acc[4][4] = {};
    for (int d = 0; d < 64; d++) {
        float c[4], bb[4];
        #pragma unroll
        for (int i = 0; i < 4; i++) c[i] = Cs[ty * 4 + i][d];
        #pragma unroll
        for (int j = 0; j < 4; j++) bb[j] = Bs2[tx * 4 + j][d];
        #pragma unroll
        for (int i = 0; i < 4; i++)
            #pragma unroll
            for (int j = 0; j < 4; j++)
                acc[i][j] += c[i] * bb[j];
    }
    #pragma unroll
    for (int i = 0; i < 4; i++)
        #pragma unroll
        for (int j = 0; j < 4; j++)
            g_G[((size_t)b * LG + l0 + ty * 4 + i) * LG + t0 + tx * 4 + j] = acc[i][j];
}

// ---------------- y = ((Lmat . G) * dt_self_t) @ x_head + x ----------------
__global__ void __launch_bounds__(256) k_final(const bf16* __restrict__ O,
                                               const float* __restrict__ x,
                                               const float* __restrict__ Dp,
                                               float* __restrict__ out) {
    int bh = blockIdx.z;
    int b = bh >> 3, h = bh & 7;
    int l0 = blockIdx.x * 64;
    size_t boff = (size_t)bh << 20;
    const float* Gb = g_G + (size_t)b * LG * LG;

    __shared__ float Os[64][65];
    __shared__ float Gs[64][65];
    __shared__ float xs[64][17];
    __shared__ float ws[64];

    int tid = threadIdx.x;
    int l = tid & 63;
    int d0 = (tid >> 6) * 4;
    float acc[4] = {0.f, 0.f, 0.f, 0.f};

    for (int t0 = 0; t0 < LG; t0 += 64) {
        #pragma unroll
        for (int q = 0; q < 2; q++) {
            int idx = tid + q * 256;
            int r = idx >> 3, c8 = (idx & 7) * 8;
            uint4 qh = *(const uint4*)(O + boff + (size_t)(l0 + r) * LG + t0 + c8);
            uint4 ql = *(const uint4*)(O + MSZ + boff + (size_t)(l0 + r) * LG + t0 + c8);
            const uint32_t* hh = (const uint32_t*)&qh;
            const uint32_t* ll = (const uint32_t*)&ql;
            #pragma unroll
            for (int p = 0; p < 4; p++) {
                Os[r][c8 + 2 * p]     = bf_lo(hh[p]) + bf_lo(ll[p]);
                Os[r][c8 + 2 * p + 1] = bf_hi(hh[p]) + bf_hi(ll[p]);
            }
        }
        #pragma unroll
        for (int q = 0; q < 4; q++) {
            int idx = tid + q * 256;
            int r = idx >> 4, c4 = (idx & 15) * 4;
            float4 g = *(const float4*)(Gb + (size_t)(l0 + r) * LG + t0 + c4);
            Gs[r][c4] = g.x; Gs[r][c4 + 1] = g.y; Gs[r][c4 + 2] = g.z; Gs[r][c4 + 3] = g.w;
        }
        {
            int t = tid >> 2, d4 = (tid & 3) * 4;
            float4 v = *(const float4*)(x + (size_t)(b * LG + t0 + t) * 128 + h * HD + d4);
            xs[t][d4] = v.x; xs[t][d4 + 1] = v.y; xs[t][d4 + 2] = v.z; xs[t][d4 + 3] = v.w;
        }
        if (tid < 64) ws[tid] = g_w[h * NN_NODES + b * LG + t0 + tid];
        __syncthreads();
        #pragma unroll 8
        for (int tt = 0; tt < 64; tt++) {
            float a = Os[l][tt] * Gs[l][tt] * ws[tt];
            #pragma unroll
            for (int j = 0; j < 4; j++) acc[j] += a * xs[tt][d0 + j];
        }
        __syncthreads();
    }

    float dh = Dp[h];
    int n = b * LG + l0 + l;
    #pragma unroll
    for (int j = 0; j < 4; j++) {
        float xv = x[(size_t)n * 128 + h * HD + d0 + j];
        out[(size_t)n * 128 + (d0 + j) * NH + h] = acc[j] + xv * dh;
    }
}

// ---------------- host launcher ----------------
extern "C" void kernel_launch(void* const* d_in, const int* in_sizes, int n_in,
                              void* d_out, int out_size) {
    const float* x   = (const float*)d_in[0];
    const float* Bm  = (const float*)d_in[1];
    const float* Cm  = (const float*)d_in[2];
    const float* dt  = (const float*)d_in[3];
    const float* dtb = (const float*)d_in[4];
    const float* Dp  = (const float*)d_in[5];
    const int*   ei  = (const int*)  d_in[6];
    float* out = (float*)d_out;

    float* S;
    cudaGetSymbolAddress((void**)&S, g_S);
    bf16 *la, *lat, *lb, *lbt, *oa, *ob;
    cudaGetSymbolAddress((void**)&la,  g_La);
    cudaGetSymbolAddress((void**)&lat, g_LaT);
    cudaGetSymbolAddress((void**)&lb,  g_Lb);
    cudaGetSymbolAddress((void**)&lbt, g_LbT);
    cudaGetSymbolAddress((void**)&oa,  g_Oa);
    cudaGetSymbolAddress((void**)&ob,  g_Ob);

    cudaFuncSetAttribute(k_mma, cudaFuncAttributeMaxDynamicSharedMemorySize, MMA_SMEM);

    k_zeronode<<<2048, 256>>>(dt, dtb, S);
    k_scatter<<<(NE * NH) / 256, 256>>>(ei);
    k_normprep<<<dim3(32, 64), 256>>>();
    // after normprep: la = M, lat = M^T, oa = I+M

    // phase 0: lb = M^2 (A=la, B=lat), transposed copy into lbt
    k_mma<<<dim3(8, 8, NB), 256, MMA_SMEM>>>(la, lat, lb, nullptr, lbt,
                                             la, lat, lb, nullptr, lbt, NB);

    // phases 1..4: combined  { ob = oa@lb + oa  |  la' = lb@lb (+ transpose) }
    for (int i = 0; i < 4; i++) {
        k_mma<<<dim3(8, 8, 2 * NB), 256, MMA_SMEM>>>(oa, lbt, ob, oa, nullptr,
                                                     lb, lbt, la, nullptr, lat, NB);
        bf16* t;
        t = oa; oa = ob;  ob = t;     // out advanced
        t = la; la = lb;  lb = t;     // lb now holds the new square
        t = lat; lat = lbt; lbt = t;
    }

    // phase 5: final out update  ob = oa@lb(M^32) + oa
    k_mma<<<dim3(8, 8, NB), 256, MMA_SMEM>>>(oa, lbt, ob, oa, nullptr,
                                             oa, lbt, ob, oa, nullptr, NB);

    k_gmat<<<dim3(16, 16, NG), 256>>>(Cm, Bm);
    k_final<<<dim3(16, 1, NB), 256>>>(ob, x, Dp, out);
}

// round 16
// speedup vs baseline: 3.1985x; 3.1985x over previous
#include <cuda_runtime.h>
#include <cuda_fp16.h>
#include <stdint.h>
#include <math.h>

#define NG 8
#define LG 1024
#define NH 8
#define HD 16
#define DS 64
#define NB 64
#define NE 131072
#define NN_NODES 8192
#define MSZ (64ULL * 1024 * 1024)

typedef __half hf;

__device__ float g_S[MSZ];
__device__ float g_G[8ULL * 1024 * 1024];
// each logical matrix: hi plane at [0, MSZ), lo plane at [MSZ, 2*MSZ)
__device__ hf g_La[2 * MSZ], g_LaT[2 * MSZ];
__device__ hf g_Lb[2 * MSZ], g_LbT[2 * MSZ];
__device__ hf g_Oa[2 * MSZ], g_Ob[2 * MSZ];
__device__ float g_e0[NH * NN_NODES];
__device__ float g_e1[NH * NN_NODES];
__device__ float g_dummy[NH * NN_NODES];
__device__ float g_w[NH * NN_NODES];

// ---------------- helpers ----------------
__device__ __forceinline__ uint32_t smem_u32(const void* p) {
    uint32_t a;
    asm("{ .reg .u64 t; cvta.to.shared.u64 t, %1; cvt.u32.u64 %0, t; }" : "=r"(a) : "l"(p));
    return a;
}
#define CP16(dst, src) asm volatile("cp.async.cg.shared.global [%0], [%1], 16;" :: "r"(dst), "l"(src) : "memory")
#define CP_COMMIT()    asm volatile("cp.async.commit_group;" ::: "memory")
#define CP_WAIT1()     asm volatile("cp.async.wait_group 1;" ::: "memory")
#define CP_WAIT0()     asm volatile("cp.async.wait_group 0;" ::: "memory")

#define LDSM4(r, addr) \
    asm volatile("ldmatrix.sync.aligned.m8n8.x4.shared.b16 {%0,%1,%2,%3}, [%4];" \
        : "=r"((r)[0]), "=r"((r)[1]), "=r"((r)[2]), "=r"((r)[3]) : "r"(addr))

#define MMA16816(d, a, b0, b1) \
    asm volatile("mma.sync.aligned.m16n8k16.row.col.f32.f16.f16.f32 " \
        "{%0,%1,%2,%3}, {%4,%5,%6,%7}, {%8,%9}, {%0,%1,%2,%3};" \
        : "+f"((d)[0]), "+f"((d)[1]), "+f"((d)[2]), "+f"((d)[3]) \
        : "r"((a)[0]), "r"((a)[1]), "r"((a)[2]), "r"((a)[3]), "r"(b0), "r"(b1))

__device__ __forceinline__ float hf_lo(uint32_t u) { return __half2float(__ushort_as_half((unsigned short)(u & 0xFFFF))); }
__device__ __forceinline__ float hf_hi(uint32_t u) { return __half2float(__ushort_as_half((unsigned short)(u >> 16))); }
__device__ __forceinline__ void split_f16(float v, hf& h, hf& l) {
    h = __float2half_rn(v);
    l = __float2half_rn(v - __half2float(h));
}
__device__ __forceinline__ uint32_t pack2(hf a, hf b) {
    return ((uint32_t)__half_as_ushort(b) << 16) | __half_as_ushort(a);
}
__device__ __forceinline__ float softplusf(float x) { return (x > 15.f) ? x : log1pf(expf(x)); }

// swizzled offset inside a 128-row x 64B operand block: row r, 16B-chunk c (0..3)
__device__ __forceinline__ uint32_t swz(int r, int c) {
    return (uint32_t)(r * 64 + ((c ^ (r >> 1)) & 3) * 16);
}

// ---------------- fused zero + per-node prep ----------------
__global__ void k_zeronode(const float* __restrict__ dt, const float* __restrict__ dtb,
                           float* __restrict__ S) {
    int gid = blockIdx.x * blockDim.x + threadIdx.x;
    if (gid < NN_NODES * NH) {
        int n = gid >> 3, h = gid & 7;
        float b = dtb[h];
        const float* row = dt + (size_t)n * (NH * 4) + h * 4;
        g_e0[h * NN_NODES + n] = -softplusf(row[0] + b);
        g_e1[h * NN_NODES + n] = -softplusf(row[1] + b);
        g_dummy[h * NN_NODES + n] = expf(-softplusf(row[2] + b));
        g_w[h * NN_NODES + n] = row[3];
    }
    size_t i = (size_t)gid * 4;
    size_t st = (size_t)gridDim.x * blockDim.x * 4;
    float4 z = make_float4(0.f, 0.f, 0.f, 0.f);
    for (; i < MSZ; i += st) *(float4*)(S + i) = z;
}

// ---------------- edge scatter ----------------
__global__ void k_scatter(const int* __restrict__ ei) {
    int idx = blockIdx.x * blockDim.x + threadIdx.x;
    if (idx >= NE * NH) return;
    int e = idx >> 3, h = idx & 7;
    int s = ei[e], d = ei[NE + e];
    int b = s >> 10, sl = s & 1023, dl = d & 1023;
    float v = expf(0.5f * (g_e0[h * NN_NODES + s] + g_e1[h * NN_NODES + d]));
    atomicAdd(&g_S[(((size_t)(b * NH + h)) * LG + sl) * LG + dl], v);
}

// ---------------- fused norm + prep ----------------
__global__ void __launch_bounds__(256) k_normprep() {
    __shared__ float snrm[32];
    __shared__ float t[32][33];
    int bh = blockIdx.y;
    int j0 = blockIdx.x * 32;
    int b = bh >> 3, h = bh & 7;
    size_t off = (size_t)bh << 20;
    int tid = threadIdx.x;
    int wid = tid >> 5, lane = tid & 31;

    #pragma unroll
    for (int rr = 0; rr < 4; rr++) {
        int jj = wid * 4 + rr;
        const float* row = g_S + off + (size_t)(j0 + jj) * LG;
        float s = 0.f;
        for (int i = lane; i < LG; i += 32) s += row[i];
        #pragma unroll
        for (int o = 16; o; o >>= 1) s += __shfl_xor_sync(0xFFFFFFFFu, s, o);
        if (lane == 0)
            snrm[jj] = 1.f / (s + g_dummy[h * NN_NODES + b * LG + j0 + jj] + 0.1f);
    }
    __syncthreads();

    int tx = tid & 31, ty = tid >> 5;   // (32, 8)
    for (int i0 = 0; i0 < LG; i0 += 32) {
        #pragma unroll
        for (int k = 0; k < 4; k++) {
            int jj = ty + k * 8;
            float v = g_S[off + (size_t)(j0 + jj) * LG + i0 + tx];
            t[jj][tx] = v;
            float mt = v * snrm[jj];
            size_t o = off + (size_t)(j0 + jj) * LG + i0 + tx;
            hf hh, ll; split_f16(mt, hh, ll);
            g_LaT[o] = hh; g_LaT[MSZ + o] = ll;
        }
        __syncthreads();
        #pragma unroll
        for (int k = 0; k < 4; k++) {
            int i = i0 + ty + k * 8;
            int j = j0 + tx;
            float v = t[tx][ty + k * 8] * snrm[tx];
            size_t o = off + (size_t)i * LG + j;
            hf hh, ll; split_f16(v, hh, ll);
            g_La[o] = hh; g_La[MSZ + o] = ll;
            float w = v + ((i == j) ? 1.f : 0.f);
            split_f16(w, hh, ll);
            g_Oa[o] = hh; g_Oa[MSZ + o] = ll;
        }
        __syncthreads();
    }
}

// ---------------- HMMA batched GEMM body: C = A@B (+Add), split fp16 x2 ----------------
// C ~= Ah*Bh + Ah*Bl  (A-lo plane never loaded into smem)
// Tile 128x128, warp tile 64x32, KC=32, 3-stage, XOR-swizzled 64B rows, 1 barrier/kt.
// Stage layout: A-hi@0 (8K) | B-hi@8192 (8K) | B-lo@16384 (8K) = 24KB.
#define STAGE_SZ 24576
#define MMA_SMEM (3 * STAGE_SZ)

__device__ __forceinline__ void mma_body(const hf* __restrict__ A,
                                         const hf* __restrict__ B,
                                         hf* __restrict__ C,
                                         const hf* __restrict__ Add,
                                         hf* __restrict__ T,
                                         char* dsm, int zb,
                                         int bx, int by, int tid) {
    size_t moff = (size_t)zb << 20;
    A += moff; B += moff; C += moff;
    if (Add) Add += moff;
    if (T) T += moff;
    int row0 = by * 128, col0 = bx * 128;

    uint32_t sm0 = smem_u32(dsm);
    int wid = tid >> 5, lane = tid & 31;
    int wm = (wid >> 2) * 64, wn = (wid & 3) * 32;

    float acc[4][4][4];
    #pragma unroll
    for (int i = 0; i < 4; i++)
        #pragma unroll
        for (int j = 0; j < 4; j++)
            #pragma unroll
            for (int k = 0; k < 4; k++) acc[i][j][k] = 0.f;

    const int r0c = tid >> 2, c0c = tid & 3;

    auto preloadA = [&](int kt, uint32_t base) {
        #pragma unroll
        for (int q = 0; q < 2; q++) {
            int r = r0c + q * 64;
            uint32_t so = swz(r, c0c);
            size_t go = (size_t)(row0 + r) * 1024 + kt * 32 + c0c * 8;
            CP16(base + so, (const char*)(A + go));                // A-hi only
        }
    };
    auto preloadB = [&](int kt, uint32_t base) {
        #pragma unroll
        for (int q = 0; q < 2; q++) {
            int r = r0c + q * 64;
            uint32_t so = swz(r, c0c);
            size_t gb = (size_t)(col0 + r) * 1024 + kt * 32 + c0c * 8;
            CP16(base + 8192 + so,  (const char*)(B + gb));        // B-hi
            CP16(base + 16384 + so, (const char*)(B + MSZ + gb));  // B-lo
        }
        CP_COMMIT();
    };

    // persistent B fragments (carried across the step boundary for kh0)
    uint32_t bhf[2][4], blf[2][4];

    auto loadB = [&](uint32_t ab, int kh) {
        #pragma unroll
        for (int nj = 0; nj < 2; nj++) {
            int br = wn + nj * 16 + (lane & 15);
            uint32_t bd = ab + 8192 + swz(br, kh * 2 + (lane >> 4));
            LDSM4(bhf[nj], bd);
            LDSM4(blf[nj], bd + 8192);
        }
    };

    auto computeA = [&](uint32_t ab, int kh) {
        #pragma unroll
        for (int mi = 0; mi < 4; mi++) {
            uint32_t ah[4];
            int ar = wm + mi * 16 + (lane & 15);
            uint32_t ad = ab + swz(ar, kh * 2 + (lane >> 4));
            LDSM4(ah, ad);
            #pragma unroll
            for (int ni = 0; ni < 4; ni++) {
                int g = ni >> 1, w = ni & 1;
                MMA16816(acc[mi][ni], ah, bhf[g][w], bhf[g][2 + w]);   // Ah*Bh
            }
            #pragma unroll
            for (int ni = 0; ni < 4; ni++) {
                int g = ni >> 1, w = ni & 1;
                MMA16816(acc[mi][ni], ah, blf[g][w], blf[g][2 + w]);   // Ah*Bl
            }
        }
    };

    // mode: 0 = prefetch kt+2 + normal tail; 1 = no prefetch, tail WAIT0; 2 = last, no tail
    auto step = [&](int kt, uint32_t ab, uint32_t nb, uint32_t pb, int mode) {
        // entry: kh0 B-frags for kt already in regs; stage ab data visible
        if (mode == 0) preloadA(kt + 2, pb);
        computeA(ab, 0);
        loadB(ab, 1);
        if (mode == 0) preloadB(kt + 2, pb);   // commit
        computeA(ab, 1);
        if (mode != 2) {
            if (mode == 1) CP_WAIT0(); else CP_WAIT1();   // own copies of G(kt+1) done
            __syncthreads();                              // visibility + stage-reuse protection
            loadB(nb, 0);                                 // next kt kh0 B-frags
        }
    };

    const uint32_t s0 = sm0, s1 = sm0 + STAGE_SZ, s2 = sm0 + 2 * STAGE_SZ;
    preloadA(0, s0); preloadB(0, s0);
    preloadA(1, s1); preloadB(1, s1);
    CP_WAIT1();          // own G0 copies done
    __syncthreads();     // all G0 copies visible
    loadB(s0, 0);        // kt0 kh0 B-frags

    for (int ktb = 0; ktb < 30; ktb += 3) {
        step(ktb,     s0, s1, s2, 0);
        step(ktb + 1, s1, s2, s0, 0);
        step(ktb + 2, s2, s0, s1, 0);
    }
    step(30, s0, s1, s2, 1);
    step(31, s1, s2, s0, 2);

    // ---- epilogue ----
    __syncthreads();   // smem reuse for transpose staging
    uint32_t* tb_h = (uint32_t*)dsm;          // [128][65] packed fp16x2
    uint32_t* tb_l = tb_h + 128 * 65;

    int rl = lane >> 2, cl = (lane & 3) * 2;
    #pragma unroll
    for (int mi = 0; mi < 4; mi++) {
        #pragma unroll
        for (int ni = 0; ni < 4; ni++) {
            int r1 = wm + mi * 16 + rl;
            int cc = wn + ni * 8 + cl;
            size_t rA = (size_t)(row0 + r1) * 1024 + col0 + cc;
            size_t rB = rA + 8 * 1024;
            float v0 = acc[mi][ni][0], v1 = acc[mi][ni][1];
            float v2 = acc[mi][ni][2], v3 = acc[mi][ni][3];
            if (Add) {
                uint32_t qh = *(const uint32_t*)(Add + rA), ql = *(const uint32_t*)(Add + MSZ + rA);
                v0 += hf_lo(qh) + hf_lo(ql);  v1 += hf_hi(qh) + hf_hi(ql);
                uint32_t rh = *(const uint32_t*)(Add + rB), rlq = *(const uint32_t*)(Add + MSZ + rB);
                v2 += hf_lo(rh) + hf_lo(rlq); v3 += hf_hi(rh) + hf_hi(rlq);
            }
            hf h0, l0, h1, l1;
            split_f16(v0, h0, l0); split_f16(v1, h1, l1);
            uint32_t ohA = pack2(h0, h1), olA = pack2(l0, l1);
            split_f16(v2, h0, l0); split_f16(v3, h1, l1);
            uint32_t ohB = pack2(h0, h1), olB = pack2(l0, l1);
            *(uint32_t*)(C + rA) = ohA;  *(uint32_t*)(C + MSZ + rA) = olA;
            *(uint32_t*)(C + rB) = ohB;  *(uint32_t*)(C + MSZ + rB) = olB;
            if (T) {
                tb_h[r1 * 65 + (cc >> 1)] = ohA;  tb_l[r1 * 65 + (cc >> 1)] = olA;
                tb_h[(r1 + 8) * 65 + (cc >> 1)] = ohB;  tb_l[(r1 + 8) * 65 + (cc >> 1)] = olB;
            }
        }
    }

    if (T) {
        __syncthreads();
        int c = tid >> 1, r0 = (tid & 1) * 64;
        const hf* b16;
        size_t to = (size_t)(col0 + c) * 1024 + row0 + r0;
        b16 = (const hf*)tb_h;
        {
            uint32_t o[32];
            #pragma unroll
            for (int r = 0; r < 64; r += 2)
                o[r >> 1] = pack2(b16[(r0 + r) * 130 + c], b16[(r0 + r + 1) * 130 + c]);
            #pragma unroll
            for (int w = 0; w < 8; w++)
                *(uint4*)(T + to + w * 8) = make_uint4(o[w*4], o[w*4+1], o[w*4+2], o[w*4+3]);
        }
        b16 = (const hf*)tb_l;
        {
            uint32_t o[32];
            #pragma unroll
            for (int r = 0; r < 64; r += 2)
                o[r >> 1] = pack2(b16[(r0 + r) * 130 + c], b16[(r0 + r + 1) * 130 + c]);
            #pragma unroll
            for (int w = 0; w < 8; w++)
                *(uint4*)(T + MSZ + to + w * 8) = make_uint4(o[w*4], o[w*4+1], o[w*4+2], o[w*4+3]);
        }
    }
}

// dual-task GEMM kernel: z < nz0 -> set 0, else set 1 (batch index z - nz0)
__global__ void __launch_bounds__(256, 2) k_mma(const hf* __restrict__ A0, const hf* __restrict__ B0,
                                                hf* __restrict__ C0, const hf* __restrict__ Add0,
                                                hf* __restrict__ T0,
                                                const hf* __restrict__ A1, const hf* __restrict__ B1,
                                                hf* __restrict__ C1, const hf* __restrict__ Add1,
                                                hf* __restrict__ T1,
                                                int nz0) {
    extern __shared__ __align__(16) char dsm[];
    int z = blockIdx.z;
    const hf *A, *B, *Add; hf *C, *T; int zb;
    if (z < nz0) { A = A0; B = B0; C = C0; Add = Add0; T = T0; zb = z; }
    else         { A = A1; B = B1; C = C1; Add = Add1; T = T1; zb = z - nz0; }
    mma_body(A, B, C, Add, T, dsm, zb, blockIdx.x, blockIdx.y, threadIdx.x);
}

// ---------------- G[b,l,t] = sum_d C[b,l,d] * B[b,t,d] ----------------
__global__ void __launch_bounds__(256) k_gmat(const float* __restrict__ Cm,
                                              const float* __restrict__ Bm) {
    __shared__ float Cs[64][65];
    __shared__ float Bs2[64][65];
    int b = blockIdx.z;
    int t0 = blockIdx.x * 64, l0 = blockIdx.y * 64;
    int tid = threadIdx.x;
    #pragma unroll
    for (int q = 0; q < 4; q++) {
        int idx = tid + q * 256;
        int r = idx >> 4, c4 = (idx & 15) * 4;
        float4 v = *(const float4*)(Cm + ((size_t)(b * LG + l0 + r)) * DS + c4);
        Cs[r][c4] = v.x; Cs[r][c4 + 1] = v.y; Cs[r][c4 + 2] = v.z; Cs[r][c4 + 3] = v.w;
        float4 w = *(const float4*)(Bm + ((size_t)(b * LG + t0 + r)) * DS + c4);
        Bs2[r][c4] = w.x; Bs2[r][c4 + 1] = w.y; Bs2[r][c4 + 2] = w.z; Bs2[r][c4 + 3] = w.w;
    }
    __syncthreads();
    int tx = tid & 15, ty = tid >> 4;
    float acc[4][4] = {};
    for (int d = 0; d < 64; d++) {
        float c[4], bb[4];
        #pragma unroll
        for (int i = 0; i < 4; i++) c[i] = Cs[ty * 4 + i][d];
        #pragma unroll
        for (int j = 0; j < 4; j++) bb[j] = Bs2[tx * 4 + j][d];
        #pragma unroll
        for (int i = 0; i < 4; i++)
            #pragma unroll
            for (int j = 0; j < 4; j++)
                acc[i][j] += c[i] * bb[j];
    }
    #pragma unroll
    for (int i = 0; i < 4; i++)
        #pragma unroll
        for (int j = 0; j < 4; j++)
            g_G[((size_t)b * LG + l0 + ty * 4 + i) * LG + t0 + tx * 4 + j] = acc[i][j];
}

// ---------------- y = ((Lmat . G) * dt_self_t) @ x_head + x ----------------
__global__ void __launch_bounds__(256) k_final(const hf* __restrict__ O,
                                               const float* __restrict__ x,
                                               const float* __restrict__ Dp,
                                               float* __restrict__ out) {
    int bh = blockIdx.z;
    int b = bh >> 3, h = bh & 7;
    int l0 = blockIdx.x * 64;
    size_t boff = (size_t)bh << 20;
    const float* Gb = g_G + (size_t)b * LG * LG;

    __shared__ float Os[64][65];
    __shared__ float Gs[64][65];
    __shared__ float xs[64][17];
    __shared__ float ws[64];

    int tid = threadIdx.x;
    int l = tid & 63;
    int d0 = (tid >> 6) * 4;
    float acc[4] = {0.f, 0.f, 0.f, 0.f};

    for (int t0 = 0; t0 < LG; t0 += 64) {
        #pragma unroll
        for (int q = 0; q < 2; q++) {
            int idx = tid + q * 256;
            int r = idx >> 3, c8 = (idx & 7) * 8;
            uint4 qh = *(const uint4*)(O + boff + (size_t)(l0 + r) * LG + t0 + c8);
            uint4 ql = *(const uint4*)(O + MSZ + boff + (size_t)(l0 + r) * LG + t0 + c8);
            const uint32_t* hh = (const uint32_t*)&qh;
            const uint32_t* ll = (const uint32_t*)&ql;
            #pragma unroll
            for (int p = 0; p < 4; p++) {
                Os[r][c8 + 2 * p]     = hf_lo(hh[p]) + hf_lo(ll[p]);
                Os[r][c8 + 2 * p + 1] = hf_hi(hh[p]) + hf_hi(ll[p]);
            }
        }
        #pragma unroll
        for (int q = 0; q < 4; q++) {
            int idx = tid + q * 256;
            int r = idx >> 4, c4 = (idx & 15) * 4;
            float4 g = *(const float4*)(Gb + (size_t)(l0 + r) * LG + t0 + c4);
            Gs[r][c4] = g.x; Gs[r][c4 + 1] = g.y; Gs[r][c4 + 2] = g.z; Gs[r][c4 + 3] = g.w;
        }
        {
            int t = tid >> 2, d4 = (tid & 3) * 4;
            float4 v = *(const float4*)(x + (size_t)(b * LG + t0 + t) * 128 + h * HD + d4);
            xs[t][d4] = v.x; xs[t][d4 + 1] = v.y; xs[t][d4 + 2] = v.z; xs[t][d4 + 3] = v.w;
        }
        if (tid < 64) ws[tid] = g_w[h * NN_NODES + b * LG + t0 + tid];
        __syncthreads();
        #pragma unroll 8
        for (int tt = 0; tt < 64; tt++) {
            float a = Os[l][tt] * Gs[l][tt] * ws[tt];
            #pragma unroll
            for (int j = 0; j < 4; j++) acc[j] += a * xs[tt][d0 + j];
        }
        __syncthreads();
    }

    float dh = Dp[h];
    int n = b * LG + l0 + l;
    #pragma unroll
    for (int j = 0; j < 4; j++) {
        float xv = x[(size_t)n * 128 + h * HD + d0 + j];
        out[(size_t)n * 128 + (d0 + j) * NH + h] = acc[j] + xv * dh;
    }
}

// ---------------- host launcher ----------------
extern "C" void kernel_launch(void* const* d_in, const int* in_sizes, int n_in,
                              void* d_out, int out_size) {
    const float* x   = (const float*)d_in[0];
    const float* Bm  = (const float*)d_in[1];
    const float* Cm  = (const float*)d_in[2];
    const float* dt  = (const float*)d_in[3];
    const float* dtb = (const float*)d_in[4];
    const float* Dp  = (const float*)d_in[5];
    const int*   ei  = (const int*)  d_in[6];
    float* out = (float*)d_out;

    float* S;
    cudaGetSymbolAddress((void**)&S, g_S);
    hf *la, *lat, *lb, *lbt, *oa, *ob;
    cudaGetSymbolAddress((void**)&la,  g_La);
    cudaGetSymbolAddress((void**)&lat, g_LaT);
    cudaGetSymbolAddress((void**)&lb,  g_Lb);
    cudaGetSymbolAddress((void**)&lbt, g_LbT);
    cudaGetSymbolAddress((void**)&oa,  g_Oa);
    cudaGetSymbolAddress((void**)&ob,  g_Ob);

    cudaFuncSetAttribute(k_mma, cudaFuncAttributeMaxDynamicSharedMemorySize, MMA_SMEM);

    k_zeronode<<<2048, 256>>>(dt, dtb, S);
    k_scatter<<<(NE * NH) / 256, 256>>>(ei);
    k_normprep<<<dim3(32, 64), 256>>>();
    // after normprep: la = M, lat = M^T, oa = I+M

    // phase 0: lb = M^2 (A=la, B=lat), transposed copy into lbt
    k_mma<<<dim3(8, 8, NB), 256, MMA_SMEM>>>(la, lat, lb, nullptr, lbt,
                                             la, lat, lb, nullptr, lbt, NB);

    // phases 1..4: combined  { ob = oa@lb + oa  |  la' = lb@lb (+ transpose) }
    for (int i = 0; i < 4; i++) {
        k_mma<<<dim3(8, 8, 2 * NB), 256, MMA_SMEM>>>(oa, lbt, ob, oa, nullptr,
                                                     lb, lbt, la, nullptr, lat, NB);
        hf* t;
        t = oa; oa = ob;  ob = t;     // out advanced
        t = la; la = lb;  lb = t;     // lb now holds the new square
        t = lat; lat = lbt; lbt = t;
    }

    // phase 5: final out update  ob = oa@lb(M^32) + oa
    k_mma<<<dim3(8, 8, NB), 256, MMA_SMEM>>>(oa, lbt, ob, oa, nullptr,
                                             oa, lbt, ob, oa, nullptr, NB);

    k_gmat<<<dim3(16, 16, NG), 256>>>(Cm, Bm);
    k_final<<<dim3(16, 1, NB), 256>>>(ob, x, Dp, out);
}

// round 17
// speedup vs baseline: 3.3616x; 1.0510x over previous
#include <cuda_runtime.h>
#include <cuda_fp16.h>
#include <stdint.h>
#include <math.h>

#define NG 8
#define LG 1024
#define NH 8
#define HD 16
#define DS 64
#define NB 64
#define NE 131072
#define NN_NODES 8192
#define MSZ (64ULL * 1024 * 1024)

typedef __half hf;

__device__ float g_S[MSZ];
__device__ float g_G[8ULL * 1024 * 1024];
// each logical matrix: hi plane at [0, MSZ), lo plane at [MSZ, 2*MSZ)
__device__ hf g_La[2 * MSZ], g_LaT[2 * MSZ];
__device__ hf g_Lb[2 * MSZ], g_LbT[2 * MSZ];
__device__ hf g_Oa[2 * MSZ], g_Ob[2 * MSZ];
__device__ float g_e0[NH * NN_NODES];
__device__ float g_e1[NH * NN_NODES];
__device__ float g_dummy[NH * NN_NODES];
__device__ float g_w[NH * NN_NODES];

// ---------------- helpers ----------------
__device__ __forceinline__ uint32_t smem_u32(const void* p) {
    uint32_t a;
    asm("{ .reg .u64 t; cvta.to.shared.u64 t, %1; cvt.u32.u64 %0, t; }" : "=r"(a) : "l"(p));
    return a;
}
#define CP16(dst, src) asm volatile("cp.async.cg.shared.global [%0], [%1], 16;" :: "r"(dst), "l"(src) : "memory")

#define MBAR_INIT(a, n) asm volatile("mbarrier.init.shared.b64 [%0], %1;" :: "r"(a), "r"(n) : "memory")
#define MBAR_ARRIVE(a) asm volatile("{\n\t.reg .b64 st;\n\tmbarrier.arrive.shared.b64 st, [%0];\n\t}" :: "r"(a) : "memory")
#define CP_MBAR_ARRIVE(a) asm volatile("cp.async.mbarrier.arrive.noinc.shared.b64 [%0];" :: "r"(a) : "memory")
#define MBAR_WAIT(a, ph) do { \
    uint32_t _m = (a), _p = (uint32_t)(ph), _d; \
    asm volatile("{\n\t.reg .pred p;\n\tmbarrier.try_wait.parity.acquire.cta.shared::cta.b64 p, [%1], %2;\n\tselp.b32 %0,1,0,p;\n\t}" \
        : "=r"(_d) : "r"(_m), "r"(_p) : "memory"); \
    if (!_d) { \
        asm volatile("{\n\t.reg .pred P1;\n\tWL_%=:\n\tmbarrier.try_wait.parity.acquire.cta.shared::cta.b64 P1, [%0], %1, 0x989680;\n\t@P1 bra.uni WD_%=;\n\tbra.uni WL_%=;\n\tWD_%=:\n\t}" \
            :: "r"(_m), "r"(_p) : "memory"); \
    } } while (0)

#define LDSM4(r, addr) \
    asm volatile("ldmatrix.sync.aligned.m8n8.x4.shared.b16 {%0,%1,%2,%3}, [%4];" \
        : "=r"((r)[0]), "=r"((r)[1]), "=r"((r)[2]), "=r"((r)[3]) : "r"(addr))

#define MMA16816(d, a, b0, b1) \
    asm volatile("mma.sync.aligned.m16n8k16.row.col.f32.f16.f16.f32 " \
        "{%0,%1,%2,%3}, {%4,%5,%6,%7}, {%8,%9}, {%0,%1,%2,%3};" \
        : "+f"((d)[0]), "+f"((d)[1]), "+f"((d)[2]), "+f"((d)[3]) \
        : "r"((a)[0]), "r"((a)[1]), "r"((a)[2]), "r"((a)[3]), "r"(b0), "r"(b1))

__device__ __forceinline__ float hf_lo(uint32_t u) { return __half2float(__ushort_as_half((unsigned short)(u & 0xFFFF))); }
__device__ __forceinline__ float hf_hi(uint32_t u) { return __half2float(__ushort_as_half((unsigned short)(u >> 16))); }
__device__ __forceinline__ void split_f16(float v, hf& h, hf& l) {
    h = __float2half_rn(v);
    l = __float2half_rn(v - __half2float(h));
}
__device__ __forceinline__ uint32_t pack2(hf a, hf b) {
    return ((uint32_t)__half_as_ushort(b) << 16) | __half_as_ushort(a);
}
__device__ __forceinline__ float softplusf(float x) { return (x > 15.f) ? x : log1pf(expf(x)); }

// swizzled offset inside a 128-row x 64B operand block: row r, 16B-chunk c (0..3)
__device__ __forceinline__ uint32_t swz(int r, int c) {
    return (uint32_t)(r * 64 + ((c ^ (r >> 1)) & 3) * 16);
}

// ---------------- fused zero + per-node prep ----------------
__global__ void k_zeronode(const float* __restrict__ dt, const float* __restrict__ dtb,
                           float* __restrict__ S) {
    int gid = blockIdx.x * blockDim.x + threadIdx.x;
    if (gid < NN_NODES * NH) {
        int n = gid >> 3, h = gid & 7;
        float b = dtb[h];
        const float* row = dt + (size_t)n * (NH * 4) + h * 4;
        g_e0[h * NN_NODES + n] = -softplusf(row[0] + b);
        g_e1[h * NN_NODES + n] = -softplusf(row[1] + b);
        g_dummy[h * NN_NODES + n] = expf(-softplusf(row[2] + b));
        g_w[h * NN_NODES + n] = row[3];
    }
    size_t i = (size_t)gid * 4;
    size_t st = (size_t)gridDim.x * blockDim.x * 4;
    float4 z = make_float4(0.f, 0.f, 0.f, 0.f);
    for (; i < MSZ; i += st) *(float4*)(S + i) = z;
}

// ---------------- edge scatter ----------------
__global__ void k_scatter(const int* __restrict__ ei) {
    int idx = blockIdx.x * blockDim.x + threadIdx.x;
    if (idx >= NE * NH) return;
    int e = idx >> 3, h = idx & 7;
    int s = ei[e], d = ei[NE + e];
    int b = s >> 10, sl = s & 1023, dl = d & 1023;
    float v = expf(0.5f * (g_e0[h * NN_NODES + s] + g_e1[h * NN_NODES + d]));
    atomicAdd(&g_S[(((size_t)(b * NH + h)) * LG + sl) * LG + dl], v);
}

// ---------------- fused norm + prep ----------------
__global__ void __launch_bounds__(256) k_normprep() {
    __shared__ float snrm[32];
    __shared__ float t[32][33];
    int bh = blockIdx.y;
    int j0 = blockIdx.x * 32;
    int b = bh >> 3, h = bh & 7;
    size_t off = (size_t)bh << 20;
    int tid = threadIdx.x;
    int wid = tid >> 5, lane = tid & 31;

    #pragma unroll
    for (int rr = 0; rr < 4; rr++) {
        int jj = wid * 4 + rr;
        const float* row = g_S + off + (size_t)(j0 + jj) * LG;
        float s = 0.f;
        for (int i = lane; i < LG; i += 32) s += row[i];
        #pragma unroll
        for (int o = 16; o; o >>= 1) s += __shfl_xor_sync(0xFFFFFFFFu, s, o);
        if (lane == 0)
            snrm[jj] = 1.f / (s + g_dummy[h * NN_NODES + b * LG + j0 + jj] + 0.1f);
    }
    __syncthreads();

    int tx = tid & 31, ty = tid >> 5;   // (32, 8)
    for (int i0 = 0; i0 < LG; i0 += 32) {
        #pragma unroll
        for (int k = 0; k < 4; k++) {
            int jj = ty + k * 8;
            float v = g_S[off + (size_t)(j0 + jj) * LG + i0 + tx];
            t[jj][tx] = v;
            float mt = v * snrm[jj];
            size_t o = off + (size_t)(j0 + jj) * LG + i0 + tx;
            hf hh, ll; split_f16(mt, hh, ll);
            g_LaT[o] = hh; g_LaT[MSZ + o] = ll;
        }
        __syncthreads();
        #pragma unroll
        for (int k = 0; k < 4; k++) {
            int i = i0 + ty + k * 8;
            int j = j0 + tx;
            float v = t[tx][ty + k * 8] * snrm[tx];
            size_t o = off + (size_t)i * LG + j;
            hf hh, ll; split_f16(v, hh, ll);
            g_La[o] = hh; g_La[MSZ + o] = ll;
            float w = v + ((i == j) ? 1.f : 0.f);
            split_f16(w, hh, ll);
            g_Oa[o] = hh; g_Oa[MSZ + o] = ll;
        }
        __syncthreads();
    }
}

// ---------------- HMMA batched GEMM body: C = A@B (+Add), split fp16 x2 ----------------
// C ~= Ah*Bh + Ah*Bl. Tile 128x128, warp tile 64x32, KC=32, XOR-swizzled 64B rows.
// 4-stage mbarrier producer/consumer pipeline (no __syncthreads in mainloop):
// full[s] = stage data landed (cp.async.mbarrier.arrive, count 256, acquire-wait)
// empty[s] = all threads finished reading stage (arrive after compute, count 256)
// Stage layout: A-hi@0 (8K) | B-hi@8192 (8K) | B-lo@16384 (8K) = 24KB.
#define STAGE_SZ 24576
#define MMA_SMEM (4 * STAGE_SZ)

__device__ __forceinline__ void mma_body(const hf* __restrict__ A,
                                         const hf* __restrict__ B,
                                         hf* __restrict__ C,
                                         const hf* __restrict__ Add,
                                         hf* __restrict__ T,
                                         char* dsm, int zb,
                                         int bx, int by, int tid) {
    size_t moff = (size_t)zb << 20;
    A += moff; B += moff; C += moff;
    if (Add) Add += moff;
    if (T) T += moff;
    int row0 = by * 128, col0 = bx * 128;

    __shared__ uint64_t s_fb[4], s_eb[4];
    uint32_t sm0 = smem_u32(dsm);
    uint32_t fbB = smem_u32(s_fb), ebB = smem_u32(s_eb);
    int wid = tid >> 5, lane = tid & 31;
    int wm = (wid >> 2) * 64, wn = (wid & 3) * 32;

    if (tid == 0) {
        #pragma unroll
        for (int s = 0; s < 4; s++) {
            MBAR_INIT(fbB + s * 8, 256);
            MBAR_INIT(ebB + s * 8, 256);
        }
    }
    __syncthreads();

    float acc[4][4][4];
    #pragma unroll
    for (int i = 0; i < 4; i++)
        #pragma unroll
        for (int j = 0; j < 4; j++)
            #pragma unroll
            for (int k = 0; k < 4; k++) acc[i][j][k] = 0.f;

    const int r0c = tid >> 2, c0c = tid & 3;

    auto preloadA = [&](int kt, uint32_t base) {
        #pragma unroll
        for (int q = 0; q < 2; q++) {
            int r = r0c + q * 64;
            uint32_t so = swz(r, c0c);
            size_t go = (size_t)(row0 + r) * 1024 + kt * 32 + c0c * 8;
            CP16(base + so, (const char*)(A + go));                // A-hi only
        }
    };
    auto preloadB = [&](int kt, uint32_t base) {
        #pragma unroll
        for (int q = 0; q < 2; q++) {
            int r = r0c + q * 64;
            uint32_t so = swz(r, c0c);
            size_t gb = (size_t)(col0 + r) * 1024 + kt * 32 + c0c * 8;
            CP16(base + 8192 + so,  (const char*)(B + gb));        // B-hi
            CP16(base + 16384 + so, (const char*)(B + MSZ + gb));  // B-lo
        }
    };

    // persistent B fragments (carried across the step boundary for kh0)
    uint32_t bhf[2][4], blf[2][4];

    auto loadB = [&](uint32_t ab, int kh) {
        #pragma unroll
        for (int nj = 0; nj < 2; nj++) {
            int br = wn + nj * 16 + (lane & 15);
            uint32_t bd = ab + 8192 + swz(br, kh * 2 + (lane >> 4));
            LDSM4(bhf[nj], bd);
            LDSM4(blf[nj], bd + 8192);
        }
    };

    auto computeA = [&](uint32_t ab, int kh) {
        #pragma unroll
        for (int mi = 0; mi < 4; mi++) {
            uint32_t ah[4];
            int ar = wm + mi * 16 + (lane & 15);
            uint32_t ad = ab + swz(ar, kh * 2 + (lane >> 4));
            LDSM4(ah, ad);
            #pragma unroll
            for (int ni = 0; ni < 4; ni++) {
                int g = ni >> 1, w = ni & 1;
                MMA16816(acc[mi][ni], ah, bhf[g][w], bhf[g][2 + w]);   // Ah*Bh
            }
            #pragma unroll
            for (int ni = 0; ni < 4; ni++) {
                int g = ni >> 1, w = ni & 1;
                MMA16816(acc[mi][ni], ah, blf[g][w], blf[g][2 + w]);   // Ah*Bl
            }
        }
    };

    // ---- pipeline prologue: fill stages 0 and 1 ----
    preloadA(0, sm0);             preloadB(0, sm0);             CP_MBAR_ARRIVE(fbB);
    preloadA(1, sm0 + STAGE_SZ);  preloadB(1, sm0 + STAGE_SZ);  CP_MBAR_ARRIVE(fbB + 8);
    MBAR_WAIT(fbB, 0);            // stage 0 data landed (all threads)
    loadB(sm0, 0);                // kt0 kh0 B-frags

    // ---- mainloop: no CTA-wide barriers; warps slip against each other ----
    #pragma unroll 4
    for (int kt = 0; kt < 32; kt++) {
        const uint32_t ab = sm0 + (uint32_t)(kt & 3) * STAGE_SZ;
        computeA(ab, 0);
        loadB(ab, 1);
        if (kt < 30) {
            const int ktp = kt + 2;
            const int sp = ktp & 3;
            const uint32_t pb = sm0 + (uint32_t)sp * STAGE_SZ;
            if (ktp >= 4) MBAR_WAIT(ebB + sp * 8, ((ktp >> 2) - 1) & 1);  // stage free (kt-2 done)
            preloadA(ktp, pb);
            preloadB(ktp, pb);
            CP_MBAR_ARRIVE(fbB + sp * 8);
        }
        computeA(ab, 1);
        MBAR_ARRIVE(ebB + (kt & 3) * 8);                                   // done reading stage
        if (kt < 31) {
            MBAR_WAIT(fbB + ((kt + 1) & 3) * 8, ((kt + 1) >> 2) & 1);      // next stage landed
            loadB(sm0 + (uint32_t)((kt + 1) & 3) * STAGE_SZ, 0);           // next kh0 B-frags
        }
    }

    // ---- epilogue ----
    __syncthreads();   // smem reuse for transpose staging
    uint32_t* tb_h = (uint32_t*)dsm;          // [128][65] packed fp16x2
    uint32_t* tb_l = tb_h + 128 * 65;

    int rl = lane >> 2, cl = (lane & 3) * 2;
    #pragma unroll
    for (int mi = 0; mi < 4; mi++) {
        #pragma unroll
        for (int ni = 0; ni < 4; ni++) {
            int r1 = wm + mi * 16 + rl;
            int cc = wn + ni * 8 + cl;
            size_t rA = (size_t)(row0 + r1) * 1024 + col0 + cc;
            size_t rB = rA + 8 * 1024;
            float v0 = acc[mi][ni][0], v1 = acc[mi][ni][1];
            float v2 = acc[mi][ni][2], v3 = acc[mi][ni][3];
            if (Add) {
                uint32_t qh = *(const uint32_t*)(Add + rA), ql = *(const uint32_t*)(Add + MSZ + rA);
                v0 += hf_lo(qh) + hf_lo(ql);  v1 += hf_hi(qh) + hf_hi(ql);
                uint32_t rh = *(const uint32_t*)(Add + rB), rlq = *(const uint32_t*)(Add + MSZ + rB);
                v2 += hf_lo(rh) + hf_lo(rlq); v3 += hf_hi(rh) + hf_hi(rlq);
            }
            hf h0, l0, h1, l1;
            split_f16(v0, h0, l0); split_f16(v1, h1, l1);
            uint32_t ohA = pack2(h0, h1), olA = pack2(l0, l1);
            split_f16(v2, h0, l0); split_f16(v3, h1, l1);
            uint32_t ohB = pack2(h0, h1), olB = pack2(l0, l1);
            *(uint32_t*)(C + rA) = ohA;  *(uint32_t*)(C + MSZ + rA) = olA;
            *(uint32_t*)(C + rB) = ohB;  *(uint32_t*)(C + MSZ + rB) = olB;
            if (T) {
                tb_h[r1 * 65 + (cc >> 1)] = ohA;  tb_l[r1 * 65 + (cc >> 1)] = olA;
                tb_h[(r1 + 8) * 65 + (cc >> 1)] = ohB;  tb_l[(r1 + 8) * 65 + (cc >> 1)] = olB;
            }
        }
    }

    if (T) {
        __syncthreads();
        int c = tid >> 1, r0 = (tid & 1) * 64;
        const hf* b16;
        size_t to = (size_t)(col0 + c) * 1024 + row0 + r0;
        b16 = (const hf*)tb_h;
        {
            uint32_t o[32];
            #pragma unroll
            for (int r = 0; r < 64; r += 2)
                o[r >> 1] = pack2(b16[(r0 + r) * 130 + c], b16[(r0 + r + 1) * 130 + c]);
            #pragma unroll
            for (int w = 0; w < 8; w++)
                *(uint4*)(T + to + w * 8) = make_uint4(o[w*4], o[w*4+1], o[w*4+2], o[w*4+3]);
        }
        b16 = (const hf*)tb_l;
        {
            uint32_t o[32];
            #pragma unroll
            for (int r = 0; r < 64; r += 2)
                o[r >> 1] = pack2(b16[(r0 + r) * 130 + c], b16[(r0 + r + 1) * 130 + c]);
            #pragma unroll
            for (int w = 0; w < 8; w++)
                *(uint4*)(T + MSZ + to + w * 8) = make_uint4(o[w*4], o[w*4+1], o[w*4+2], o[w*4+3]);
        }
    }
}

// dual-task GEMM kernel: z < nz0 -> set 0, else set 1 (batch index z - nz0)
__global__ void __launch_bounds__(256, 2) k_mma(const hf* __restrict__ A0, const hf* __restrict__ B0,
                                                hf* __restrict__ C0, const hf* __restrict__ Add0,
                                                hf* __restrict__ T0,
                                                const hf* __restrict__ A1, const hf* __restrict__ B1,
                                                hf* __restrict__ C1, const hf* __restrict__ Add1,
                                                hf* __restrict__ T1,
                                                int nz0) {
    extern __shared__ __align__(16) char dsm[];
    int z = blockIdx.z;
    const hf *A, *B, *Add; hf *C, *T; int zb;
    if (z < nz0) { A = A0; B = B0; C = C0; Add = Add0; T = T0; zb = z; }
    else         { A = A1; B = B1; C = C1; Add = Add1; T = T1; zb = z - nz0; }
    mma_body(A, B, C, Add, T, dsm, zb, blockIdx.x, blockIdx.y, threadIdx.x);
}

// ---------------- G[b,l,t] = sum_d C[b,l,d] * B[b,t,d] ----------------
__global__ void __launch_bounds__(256) k_gmat(const float* __restrict__ Cm,
                                              const float* __restrict__ Bm) {
    __shared__ float Cs[64][65];
    __shared__ float Bs2[64][65];
    int b = blockIdx.z;
    int t0 = blockIdx.x * 64, l0 = blockIdx.y * 64;
    int tid = threadIdx.x;
    #pragma unroll
    for (int q = 0; q < 4; q++) {
        int idx = tid + q * 256;
        int r = idx >> 4, c4 = (idx & 15) * 4;
        float4 v = *(const float4*)(Cm + ((size_t)(b * LG + l0 + r)) * DS + c4);
        Cs[r][c4] = v.x; Cs[r][c4 + 1] = v.y; Cs[r][c4 + 2] = v.z; Cs[r][c4 + 3] = v.w;
        float4 w = *(const float4*)(Bm + ((size_t)(b * LG + t0 + r)) * DS + c4);
        Bs2[r][c4] = w.x; Bs2[r][c4 + 1] = w.y; Bs2[r][c4 + 2] = w.z; Bs2[r][c4 + 3] = w.w;
    }
    __syncthreads();
    int tx = tid & 15, ty = tid >> 4;
    float acc[4][4] = {};
    for (int d = 0; d < 64; d++) {
        float c[4], bb[4];
        #pragma unroll
        for (int i = 0; i < 4; i++) c[i] = Cs[ty * 4 + i][d];
        #pragma unroll
        for (int j = 0; j < 4; j++) bb[j] = Bs2[tx * 4 + j][d];
        #pragma unroll
        for (int i = 0; i < 4; i++)
            #pragma unroll
            for (int j = 0; j < 4; j++)
                acc[i][j] += c[i] * bb[j];
    }
    #pragma unroll
    for (int i = 0; i < 4; i++)
        #pragma unroll
        for (int j = 0; j < 4; j++)
            g_G[((size_t)b * LG + l0 + ty * 4 + i) * LG + t0 + tx * 4 + j] = acc[i][j];
}

// ---------------- y = ((Lmat . G) * dt_self_t) @ x_head + x ----------------
__global__ void __launch_bounds__(256) k_final(const hf* __restrict__ O,
                                               const float* __restrict__ x,
                                               const float* __restrict__ Dp,
                                               float* __restrict__ out) {
    int bh = blockIdx.z;
    int b = bh >> 3, h = bh & 7;
    int l0 = blockIdx.x * 64;
    size_t boff = (size_t)bh << 20;
    const float* Gb = g_G + (size_t)b * LG * LG;

    __shared__ float Os[64][65];
    __shared__ float Gs[64][65];
    __shared__ float xs[64][17];
    __shared__ float ws[64];

    int tid = threadIdx.x;
    int l = tid & 63;
    int d0 = (tid >> 6) * 4;
    float acc[4] = {0.f, 0.f, 0.f, 0.f};

    for (int t0 = 0; t0 < LG; t0 += 64) {
        #pragma unroll
        for (int q = 0; q < 2; q++) {
            int idx = tid + q * 256;
            int r = idx >> 3, c8 = (idx & 7) * 8;
            uint4 qh = *(const uint4*)(O + boff + (size_t)(l0 + r) * LG + t0 + c8);
            uint4 ql = *(const uint4*)(O + MSZ + boff + (size_t)(l0 + r) * LG + t0 + c8);
            const uint32_t* hh = (const uint32_t*)&qh;
            const uint32_t* ll = (const uint32_t*)&ql;
            #pragma unroll
            for (int p = 0; p < 4; p++) {
                Os[r][c8 + 2 * p]     = hf_lo(hh[p]) + hf_lo(ll[p]);
                Os[r][c8 + 2 * p + 1] = hf_hi(hh[p]) + hf_hi(ll[p]);
            }
        }
        #pragma unroll
        for (int q = 0; q < 4; q++) {
            int idx = tid + q * 256;
            int r = idx >> 4, c4 = (idx & 15) * 4;
            float4 g = *(const float4*)(Gb + (size_t)(l0 + r) * LG + t0 + c4);
            Gs[r][c4] = g.x; Gs[r][c4 + 1] = g.y; Gs[r][c4 + 2] = g.z; Gs[r][c4 + 3] = g.w;
        }
        {
            int t = tid >> 2, d4 = (tid & 3) * 4;
            float4 v = *(const float4*)(x + (size_t)(b * LG + t0 + t) * 128 + h * HD + d4);
            xs[t][d4] = v.x; xs[t][d4 + 1] = v.y; xs[t][d4 + 2] = v.z; xs[t][d4 + 3] = v.w;
        }
        if (tid < 64) ws[tid] = g_w[h * NN_NODES + b * LG + t0 + tid];
        __syncthreads();
        #pragma unroll 8
        for (int tt = 0; tt < 64; tt++) {
            float a = Os[l][tt] * Gs[l][tt] * ws[tt];
            #pragma unroll
            for (int j = 0; j < 4; j++) acc[j] += a * xs[tt][d0 + j];
        }
        __syncthreads();
    }

    float dh = Dp[h];
    int n = b * LG + l0 + l;
    #pragma unroll
    for (int j = 0; j < 4; j++) {
        float xv = x[(size_t)n * 128 + h * HD + d0 + j];
        out[(size_t)n * 128 + (d0 + j) * NH + h] = acc[j] + xv * dh;
    }
}

// ---------------- host launcher ----------------
extern "C" void kernel_launch(void* const* d_in, const int* in_sizes, int n_in,
                              void* d_out, int out_size) {
    const float* x   = (const float*)d_in[0];
    const float* Bm  = (const float*)d_in[1];
    const float* Cm  = (const float*)d_in[2];
    const float* dt  = (const float*)d_in[3];
    const float* dtb = (const float*)d_in[4];
    const float* Dp  = (const float*)d_in[5];
    const int*   ei  = (const int*)  d_in[6];
    float* out = (float*)d_out;

    float* S;
    cudaGetSymbolAddress((void**)&S, g_S);
    hf *la, *lat, *lb, *lbt, *oa, *ob;
    cudaGetSymbolAddress((void**)&la,  g_La);
    cudaGetSymbolAddress((void**)&lat, g_LaT);
    cudaGetSymbolAddress((void**)&lb,  g_Lb);
    cudaGetSymbolAddress((void**)&lbt, g_LbT);
    cudaGetSymbolAddress((void**)&oa,  g_Oa);
    cudaGetSymbolAddress((void**)&ob,  g_Ob);

    cudaFuncSetAttribute(k_mma, cudaFuncAttributeMaxDynamicSharedMemorySize, MMA_SMEM);

    k_zeronode<<<2048, 256>>>(dt, dtb, S);
    k_scatter<<<(NE * NH) / 256, 256>>>(ei);
    k_normprep<<<dim3(32, 64), 256>>>();
    // after normprep: la = M, lat = M^T, oa = I+M

    // phase 0: lb = M^2 (A=la, B=lat), transposed copy into lbt
    k_mma<<<dim3(8, 8, NB), 256, MMA_SMEM>>>(la, lat, lb, nullptr, lbt,
                                             la, lat, lb, nullptr, lbt, NB);

    // phases 1..4: combined  { ob = oa@lb + oa  |  la' = lb@lb (+ transpose) }
    for (int i = 0; i < 4; i++) {
        k_mma<<<dim3(8, 8, 2 * NB), 256, MMA_SMEM>>>(oa, lbt, ob, oa, nullptr,
                                                     lb, lbt, la, nullptr, lat, NB);
        hf* t;
        t = oa; oa = ob;  ob = t;     // out advanced
        t = la; la = lb;  lb = t;     // lb now holds the new square
        t = lat; lat = lbt; lbt = t;
    }

    // phase 5: final out update  ob = oa@lb(M^32) + oa
    k_mma<<<dim3(8, 8, NB), 256, MMA_SMEM>>>(oa, lbt, ob, oa, nullptr,
                                             oa, lbt, ob, oa, nullptr, NB);

    k_gmat<<<dim3(16, 16, NG), 256>>>(Cm, Bm);
    k_final<<<dim3(16, 1, NB), 256>>>(ob, x, Dp, out);
}